// round 7
// baseline (speedup 1.0000x reference)
#include <cuda_runtime.h>

#define IMG 512
#define BATCH 32
#define TW 128
#define TH 16
#define RAD 5
#define RAW_W 138        // TW + 2*RAD columns needed by stage 2
#define RS 140           // vbuf row stride (floats), multiple of 4 for float4 LDS
#define NTHREADS 256
#define NBLOCKS 4096     // (512/128) * (512/16) * 32
#define NPIX_D 8388608.0
#define G 4              // stage-1 vertical row-group size
#define NSLOTS1 (4 * RAW_W)   // 552 stage-1 slots
#define JROWS (G + 10)        // 14 raw rows feed 4 output rows

typedef unsigned long long u64;

__device__ double g_accum;          // zero-initialized at module load
__device__ unsigned int g_count;    // zero-initialized at module load

// ---- f32x2 packed-math helpers (SASS FFMA2 path; ptxas won't emit from C++) ----
__device__ __forceinline__ u64 pk2(float lo, float hi) {
    u64 r; asm("mov.b64 %0, {%1, %2};" : "=l"(r) : "f"(lo), "f"(hi)); return r;
}
__device__ __forceinline__ void upk2(u64 v, float& lo, float& hi) {
    asm("mov.b64 {%0, %1}, %2;" : "=f"(lo), "=f"(hi) : "l"(v));
}
__device__ __forceinline__ u64 fma2_(u64 a, u64 b, u64 c) {
    u64 d; asm("fma.rn.f32x2 %0, %1, %2, %3;" : "=l"(d) : "l"(a), "l"(b), "l"(c)); return d;
}
__device__ __forceinline__ u64 mul2_(u64 a, u64 b) {
    u64 d; asm("mul.rn.f32x2 %0, %1, %2;" : "=l"(d) : "l"(a), "l"(b)); return d;
}
__device__ __forceinline__ u64 add2_(u64 a, u64 b) {
    u64 d; asm("add.rn.f32x2 %0, %1, %2;" : "=l"(d) : "l"(a), "l"(b)); return d;
}

// Normalized 1-D Gaussian, sigma=1.5, K=11; symmetric W[d]=W[10-d]
#define W0 0.00102838f
#define W1 0.00759876f
#define W2c 0.03600078f
#define W3 0.10936070f
#define W4 0.21300554f
#define W5 0.26601172f
__device__ __forceinline__ float wgt(int d) {
    const float WH[6] = {W0, W1, W2c, W3, W4, W5};
    return WH[d < 6 ? d : 10 - d];
}

// Horizontal 11-tap conv over a (rowA,rowB) y-pair, 4 outputs, f32x2-packed.
__device__ __forceinline__ void hconv2(const float* __restrict__ rA,
                                       const float* __restrict__ rB,
                                       const u64* __restrict__ Wp, u64 out[4]) {
    float A[14], B[14];
    {   // conflict-free wide loads (16B thread stride across the warp)
        float4 a0 = *(const float4*)(rA);      float4 b0 = *(const float4*)(rB);
        float4 a1 = *(const float4*)(rA + 4);  float4 b1 = *(const float4*)(rB + 4);
        float4 a2 = *(const float4*)(rA + 8);  float4 b2 = *(const float4*)(rB + 8);
        float2 a3 = *(const float2*)(rA + 12); float2 b3 = *(const float2*)(rB + 12);
        A[0]=a0.x; A[1]=a0.y; A[2]=a0.z; A[3]=a0.w; A[4]=a1.x; A[5]=a1.y; A[6]=a1.z;
        A[7]=a1.w; A[8]=a2.x; A[9]=a2.y; A[10]=a2.z; A[11]=a2.w; A[12]=a3.x; A[13]=a3.y;
        B[0]=b0.x; B[1]=b0.y; B[2]=b0.z; B[3]=b0.w; B[4]=b1.x; B[5]=b1.y; B[6]=b1.z;
        B[7]=b1.w; B[8]=b2.x; B[9]=b2.y; B[10]=b2.z; B[11]=b2.w; B[12]=b3.x; B[13]=b3.y;
    }
    out[0] = out[1] = out[2] = out[3] = 0ull;
    #pragma unroll
    for (int j = 0; j < 14; j++) {
        u64 p = pk2(A[j], B[j]);
        #pragma unroll
        for (int o = 0; o < 4; o++) {
            const int d = j - o;
            if (d >= 0 && d < 11)
                out[o] = fma2_(Wp[d < 6 ? d : 10 - d], p, out[o]);
        }
    }
}

__global__ __launch_bounds__(NTHREADS, 4)
void ssim_main_kernel(const float* __restrict__ img1, const float* __restrict__ img2,
                      float* __restrict__ out) {
    extern __shared__ float sm[];
    float* vb0 = sm;                    // 5 planes, each 16*140
    float* vb1 = sm + 1 * TH * RS;
    float* vb2 = sm + 2 * TH * RS;
    float* vb3 = sm + 3 * TH * RS;
    float* vb4 = sm + 4 * TH * RS;
    float* red = sm + 5 * TH * RS;      // 8 floats

    u64 Wp[6];
    #pragma unroll
    for (int d = 0; d < 6; d++) { float w = wgt(d); Wp[d] = pk2(w, w); }

    const int tid = threadIdx.x;
    const int bx0 = blockIdx.x * TW - RAD;
    const int by0 = blockIdx.y * TH - RAD;
    const long ib = (long)blockIdx.z * IMG * IMG;

    // ---- stage 1: vertical 11-tap conv, f32x2-packed across (a,b)/(a2,b2) ----
    for (int s = tid; s < NSLOTS1; s += NTHREADS) {
        int grp = s / RAW_W;
        int col = s - grp * RAW_W;          // 0..137
        int ybase = grp * G;
        int gx = bx0 + col;
        int gybase = by0 + ybase;
        const bool xin = (gx >= 0) & (gx < IMG);
        const float* p1 = img1 + ib + (long)gybase * IMG + gx;
        const float* p2 = img2 + ib + (long)gybase * IMG + gx;

        u64 a01[G] = {0,0,0,0};             // packed {conv(a), conv(b)}
        u64 a23[G] = {0,0,0,0};             // packed {conv(a2), conv(b2)}
        float a4[G] = {0,0,0,0};            // conv(ab)
        #pragma unroll
        for (int j = 0; j < JROWS; j++) {
            int gy = gybase + j;
            bool in = xin & (gy >= 0) & (gy < IMG);
            float av = in ? p1[j * IMG] : 0.f;
            float bv = in ? p2[j * IMG] : 0.f;
            float ab = av * bv;
            u64 pab = pk2(av, bv);
            u64 pqq = mul2_(pab, pab);      // {a^2, b^2}
            #pragma unroll
            for (int o = 0; o < G; o++) {
                const int d = j - o;
                if (d >= 0 && d < 11) {
                    const u64 wd = Wp[d < 6 ? d : 10 - d];
                    a01[o] = fma2_(wd, pab, a01[o]);
                    a23[o] = fma2_(wd, pqq, a23[o]);
                    a4[o] = fmaf(wgt(d), ab, a4[o]);
                }
            }
        }
        #pragma unroll
        for (int o = 0; o < G; o++) {
            int idx = (ybase + o) * RS + col;
            float v0, v1, v2, v3;
            upk2(a01[o], v0, v1);
            upk2(a23[o], v2, v3);
            vb0[idx] = v0;
            vb1[idx] = v1;
            vb2[idx] = v2;
            vb3[idx] = v3;
            vb4[idx] = a4[o];
        }
    }
    __syncthreads();

    // ---- stage 2: horizontal conv packed across y-pair (yp, yp+8) + SSIM ----
    float lsum = 0.f;
    {
        int xg = tid & 31;                  // 32 x-groups * 8 y-pairs = 256 slots
        int yp = tid >> 5;                  // 0..7 -> rows yp and yp+8
        int x0 = xg * 4;                    // 16B-aligned
        const int rowoff = yp * RS + x0;

        u64 m1[4], m2[4], mu12[4], musq[4], t23[4], racc[4];

        hconv2(vb0 + rowoff, vb0 + rowoff + 8 * RS, Wp, m1);
        hconv2(vb1 + rowoff, vb1 + rowoff + 8 * RS, Wp, m2);
        #pragma unroll
        for (int o = 0; o < 4; o++) {
            mu12[o] = mul2_(m1[o], m2[o]);
            musq[o] = fma2_(m2[o], m2[o], mul2_(m1[o], m1[o]));
        }
        hconv2(vb2 + rowoff, vb2 + rowoff + 8 * RS, Wp, t23);
        hconv2(vb3 + rowoff, vb3 + rowoff + 8 * RS, Wp, racc);
        #pragma unroll
        for (int o = 0; o < 4; o++) t23[o] = add2_(t23[o], racc[o]);
        hconv2(vb4 + rowoff, vb4 + rowoff + 8 * RS, Wp, racc);   // E[ab]

        const u64 NEG1 = pk2(-1.f, -1.f);
        const u64 C1v  = pk2(0.0001f, 0.0001f);
        const u64 C2v  = pk2(0.0009f, 0.0009f);
        #pragma unroll
        for (int o = 0; o < 4; o++) {
            u64 s12  = fma2_(mu12[o], NEG1, racc[o]);       // E[ab] - mu1*mu2
            u64 sigs = fma2_(musq[o], NEG1, t23[o]);        // s1 + s2
            u64 num  = mul2_(add2_(add2_(mu12[o], mu12[o]), C1v),
                             add2_(add2_(s12, s12), C2v));
            u64 den  = mul2_(add2_(musq[o], C1v), add2_(sigs, C2v));
            float n0, n1, d0, d1;
            upk2(num, n0, n1);
            upk2(den, d0, d1);
            lsum += __fdividef(n0, d0) + __fdividef(n1, d1);
        }
    }

    // ---- block reduction ----
    #pragma unroll
    for (int off = 16; off > 0; off >>= 1)
        lsum += __shfl_xor_sync(0xffffffff, lsum, off);
    if ((tid & 31) == 0) red[tid >> 5] = lsum;
    __syncthreads();

    // ---- single-kernel finalize ----
    if (tid == 0) {
        float v = red[0] + red[1] + red[2] + red[3] +
                  red[4] + red[5] + red[6] + red[7];
        atomicAdd(&g_accum, (double)v);
        __threadfence();
        unsigned int ticket = atomicAdd(&g_count, 1u);
        if (ticket == NBLOCKS - 1) {
            double sfin = atomicAdd(&g_accum, 0.0);
            out[0] = (float)(1.0 - sfin / NPIX_D);
            g_accum = 0.0;
            g_count = 0u;
        }
    }
}

extern "C" void kernel_launch(void* const* d_in, const int* in_sizes, int n_in,
                              void* d_out, int out_size) {
    const float* img1 = (const float*)d_in[0];
    const float* img2 = (const float*)d_in[1];
    float* out = (float*)d_out;

    const size_t smem = (size_t)(5 * TH * RS + 8) * sizeof(float);   // ~44.9 KB
    cudaFuncSetAttribute(ssim_main_kernel,
                         cudaFuncAttributeMaxDynamicSharedMemorySize, (int)smem);

    dim3 grid(IMG / TW, IMG / TH, BATCH);   // 4 x 32 x 32 = 4096 blocks
    ssim_main_kernel<<<grid, NTHREADS, smem>>>(img1, img2, out);
}